// round 1
// baseline (speedup 1.0000x reference)
#include <cuda_runtime.h>
#include <cuda_bf16.h>

// Problem constants (fixed by the dataset problem)
#define Bq 32
#define Sq 2048
#define Dq 512
#define Hq 32
#define NTOK (Bq * Sq)          // 65536

// Shared-memory layout (floats) for the main weight kernel
#define PT_STRIDE 516           // padded row stride for transposed projector
#define HT_STRIDE 36            // padded row stride for transposed hidden
#define SM_PT_OFF 0
#define SM_HT_OFF (32 * PT_STRIDE)                 // 16512
#define SM_XS_OFF (SM_HT_OFF + 32 * HT_STRIDE)     // 17664
#define SM_WS_OFF (SM_XS_OFF + 8 * 8 * 512)        // 50432
#define SM_FLOATS (SM_WS_OFF + 8 * 256)            // 52480
#define SMEM_BYTES (SM_FLOATS * 4)                 // 209920 bytes

#define RSCALE 0.17677669529663687f   // 1/sqrt(32)

// -------------------- scratch (no allocations allowed) --------------------
__device__ int   g_mask_mode;        // 0=bool(u8), 1=int32, 2=float32
__device__ int   g_count;            // number of unmasked tokens
__device__ int   g_idx[NTOK];        // compacted unmasked token indices
__device__ float g_w[NTOK];          // exp(z) per token (0 for masked)
__device__ float g_bsum[Bq];         // per-batch weight sums
__device__ float g_partial[8][Bq * Dq];  // partial weighted sums per s-chunk

// -------------------- f32x2 helpers --------------------
__device__ __forceinline__ void fma2(unsigned long long& d,
                                     unsigned long long a,
                                     unsigned long long b) {
    asm("fma.rn.f32x2 %0, %1, %2, %3;" : "=l"(d) : "l"(a), "l"(b), "l"(d));
}
__device__ __forceinline__ float2 upk(unsigned long long v) {
    float2 r;
    asm("mov.b64 {%0, %1}, %2;" : "=f"(r.x), "=f"(r.y) : "l"(v));
    return r;
}
__device__ __forceinline__ float sigmoidf(float v) {
    return 1.0f / (1.0f + __expf(-v));
}

// -------------------- kernel 0: detect mask dtype, reset counter ----------
__global__ void k_detect(const unsigned int* m) {
    if (threadIdx.x == 0 && blockIdx.x == 0) {
        bool all_i = true, all_f = true;
        for (int i = 0; i < 256; ++i) {
            unsigned v = m[i];
            if (v > 1u) all_i = false;
            if (v != 0u && v != 0x3F800000u) all_f = false;
        }
        g_mask_mode = all_i ? 1 : (all_f ? 2 : 0);
        g_count = 0;
    }
}

// -------------------- kernel 1: compact unmasked tokens -------------------
__global__ void k_prep(const void* mask) {
    int t = blockIdx.x * blockDim.x + threadIdx.x;
    if (t >= NTOK) return;
    int mm = g_mask_mode;
    bool on;
    if (mm == 1)      on = ((const int*)mask)[t] != 0;
    else if (mm == 2) on = ((const float*)mask)[t] != 0.0f;
    else              on = ((const unsigned char*)mask)[t] != 0;
    if (on) {
        int pos = atomicAdd(&g_count, 1);
        g_idx[pos] = t;
    } else {
        g_w[t] = 0.0f;
    }
}

// -------------------- kernel 2: weight chain per unmasked token -----------
// Per block: 256 threads = 8 warps, 8 tokens per warp (4 f32x2 pairs over d).
__global__ void __launch_bounds__(256) k_main(const float* __restrict__ inp,
                                              const float* __restrict__ proj,
                                              const float* __restrict__ hid,
                                              const float* __restrict__ ev) {
    extern __shared__ float sm[];
    const int tid  = threadIdx.x;
    const int lane = tid & 31;
    const int wid  = tid >> 5;

    const int count = g_count;
    if ((int)blockIdx.x * 64 >= count) return;

    // Stage transposed projector Pt[h][d], padded stride 516 (conflict-free LDS.128)
    for (int i = tid; i < Dq * Hq; i += 256) {
        int d = i >> 5, h = i & 31;
        sm[SM_PT_OFF + h * PT_STRIDE + d] = proj[i];
    }
    // Stage transposed hidden Ht[k][h], padded stride 36
    for (int i = tid; i < Hq * Hq; i += 256) {
        int h = i >> 5, k = i & 31;
        sm[SM_HT_OFF + k * HT_STRIDE + h] = hid[i];
    }
    const float evv = ev[lane];
    __syncthreads();

    float* Xw  = sm + SM_XS_OFF + wid * (8 * 512);
    float* Wsw = sm + SM_WS_OFF + wid * 256;

    int  tok[8];
    bool valid[8];
    const int base = blockIdx.x * 64 + wid * 8;
#pragma unroll
    for (int t = 0; t < 8; ++t) {
        int slot = base + t;
        valid[t] = slot < count;
        int sc   = valid[t] ? slot : (count - 1);
        tok[t]   = g_idx[sc];
    }

    // Stage 8 token rows (512 floats each) into shared memory
#pragma unroll
    for (int t = 0; t < 8; ++t) {
        const float4* src = (const float4*)(inp + (size_t)tok[t] * Dq);
        float4* dst = (float4*)(Xw + t * 512);
#pragma unroll
        for (int i = 0; i < 4; ++i)
            dst[i * 32 + lane] = src[i * 32 + lane];
    }
    __syncwarp();

    // ---- projector: p[h] = sum_d x[d] * P[d][h], lane = h, pairs over d ----
    unsigned long long acc[8];
#pragma unroll
    for (int t = 0; t < 8; ++t) acc[t] = 0ull;

    const float* PtRow = sm + SM_PT_OFF + lane * PT_STRIDE;
#pragma unroll 2
    for (int d0 = 0; d0 < 512; d0 += 8) {
        ulonglong2 pA = *(const ulonglong2*)(PtRow + d0);
        ulonglong2 pB = *(const ulonglong2*)(PtRow + d0 + 4);
#pragma unroll
        for (int t = 0; t < 8; ++t) {
            const ulonglong2* xp = (const ulonglong2*)(Xw + t * 512 + d0);
            ulonglong2 xA = xp[0];
            ulonglong2 xB = xp[1];
            fma2(acc[t], xA.x, pA.x);
            fma2(acc[t], xA.y, pA.y);
            fma2(acc[t], xB.x, pB.x);
            fma2(acc[t], xB.y, pB.y);
        }
    }

    // ---- sigmoid, stash w0 for cross-lane access ----
#pragma unroll
    for (int t = 0; t < 8; ++t) {
        float2 a = upk(acc[t]);
        float w0 = sigmoidf((a.x + a.y) * RSCALE);
        Wsw[t * 32 + lane] = w0;
    }
    __syncwarp();

    // ---- hidden layer: h1[k] = sum_h w0[h] * Hd[h][k], lane = k ----
    unsigned long long acc1[8];
#pragma unroll
    for (int t = 0; t < 8; ++t) acc1[t] = 0ull;

    const float* HtRow = sm + SM_HT_OFF + lane * HT_STRIDE;
#pragma unroll
    for (int h0 = 0; h0 < 32; h0 += 8) {
        ulonglong2 hA = *(const ulonglong2*)(HtRow + h0);
        ulonglong2 hB = *(const ulonglong2*)(HtRow + h0 + 4);
#pragma unroll
        for (int t = 0; t < 8; ++t) {
            const ulonglong2* wp = (const ulonglong2*)(Wsw + t * 32 + h0);
            ulonglong2 wA = wp[0];
            ulonglong2 wB = wp[1];
            fma2(acc1[t], wA.x, hA.x);
            fma2(acc1[t], wA.y, hA.y);
            fma2(acc1[t], wB.x, hB.x);
            fma2(acc1[t], wB.y, hB.y);
        }
    }

    // ---- evaluator + final sigmoid + exp ----
#pragma unroll
    for (int t = 0; t < 8; ++t) {
        float2 a1 = upk(acc1[t]);
        float w1 = sigmoidf((a1.x + a1.y) * RSCALE);
        float e = w1 * evv;
        e += __shfl_xor_sync(0xffffffffu, e, 16);
        e += __shfl_xor_sync(0xffffffffu, e, 8);
        e += __shfl_xor_sync(0xffffffffu, e, 4);
        e += __shfl_xor_sync(0xffffffffu, e, 2);
        e += __shfl_xor_sync(0xffffffffu, e, 1);
        float z = sigmoidf(e * RSCALE);
        float wf = __expf(z);
        if (valid[t] && lane == 0) g_w[tok[t]] = wf;
    }
}

// -------------------- kernel 3: per-batch weight sums ---------------------
__global__ void k_bsum() {
    __shared__ float red[256];
    int b = blockIdx.x;
    float s = 0.f;
    for (int i = threadIdx.x; i < Sq; i += 256) s += g_w[b * Sq + i];
    red[threadIdx.x] = s;
    __syncthreads();
    for (int off = 128; off > 0; off >>= 1) {
        if (threadIdx.x < off) red[threadIdx.x] += red[threadIdx.x + off];
        __syncthreads();
    }
    if (threadIdx.x == 0) g_bsum[b] = red[0];
}

// -------------------- kernel 4: weighted sum over sequence ----------------
// grid: 1024 blocks = 32 batches x 4 d-chunks x 8 s-chunks; 128 threads = d cols
__global__ void __launch_bounds__(128) k_wsum(const float* __restrict__ inp) {
    __shared__ float ws[256];
    const int bi = blockIdx.x;
    const int sc = bi & 7;
    const int dc = (bi >> 3) & 3;
    const int b  = bi >> 5;
    const int d  = dc * 128 + threadIdx.x;

    const float* wsrc = g_w + b * Sq + sc * 256;
    ws[threadIdx.x]       = wsrc[threadIdx.x];
    ws[threadIdx.x + 128] = wsrc[threadIdx.x + 128];
    __syncthreads();

    const float* xb = inp + ((size_t)b * Sq + sc * 256) * Dq + d;
    float a0 = 0.f, a1 = 0.f, a2 = 0.f, a3 = 0.f;
#pragma unroll 4
    for (int s = 0; s < 256; s += 4) {
        float w0 = ws[s], w1 = ws[s + 1], w2 = ws[s + 2], w3 = ws[s + 3];
        if (w0 != 0.f) a0 += w0 * xb[(size_t)(s + 0) * Dq];
        if (w1 != 0.f) a1 += w1 * xb[(size_t)(s + 1) * Dq];
        if (w2 != 0.f) a2 += w2 * xb[(size_t)(s + 2) * Dq];
        if (w3 != 0.f) a3 += w3 * xb[(size_t)(s + 3) * Dq];
    }
    g_partial[sc][b * Dq + d] = (a0 + a1) + (a2 + a3);
}

// -------------------- kernel 5: reduce partials + normalize ---------------
__global__ void k_final(float* __restrict__ out) {
    int i = blockIdx.x * 256 + threadIdx.x;   // 16384 outputs
    int b = i >> 9;
    float s = 0.f;
#pragma unroll
    for (int k = 0; k < 8; ++k) s += g_partial[k][i];
    out[i] = s / g_bsum[b];
}

// -------------------- launcher --------------------
extern "C" void kernel_launch(void* const* d_in, const int* in_sizes, int n_in,
                              void* d_out, int out_size) {
    const float* inp  = (const float*)d_in[0];
    const void*  mask = d_in[1];
    const float* proj = (const float*)d_in[2];
    const float* hid  = (const float*)d_in[3];
    const float* ev   = (const float*)d_in[4];
    float* out = (float*)d_out;

    cudaFuncSetAttribute(k_main, cudaFuncAttributeMaxDynamicSharedMemorySize,
                         SMEM_BYTES);

    k_detect<<<1, 32>>>((const unsigned int*)mask);
    k_prep<<<NTOK / 256, 256>>>(mask);
    k_main<<<NTOK / 64, 256, SMEM_BYTES>>>(inp, proj, hid, ev);
    k_bsum<<<Bq, 256>>>();
    k_wsum<<<Bq * 4 * 8, 128>>>(inp);
    k_final<<<Bq * Dq / 256, 256>>>(out);
}

// round 2
// speedup vs baseline: 1.2437x; 1.2437x over previous
#include <cuda_runtime.h>
#include <cuda_bf16.h>

// Problem constants (fixed by the dataset problem)
#define Bq 32
#define Sq 2048
#define Dq 512
#define Hq 32
#define NTOK (Bq * Sq)          // 65536

// Shared-memory layout (floats) for the main weight kernel
#define PT_STRIDE 516           // padded row stride for transposed projector
#define HT_STRIDE 36            // padded row stride for transposed hidden
#define SM_PT_OFF 0
#define SM_HT_OFF (32 * PT_STRIDE)                 // 16512
#define SM_XS_OFF (SM_HT_OFF + 32 * HT_STRIDE)     // 17664
#define SM_WS_OFF (SM_XS_OFF + 8 * 8 * 512)        // 50432
#define SM_FLOATS (SM_WS_OFF + 8 * 256)            // 52480
#define SMEM_BYTES (SM_FLOATS * 4)                 // 209920 bytes

// Epilogue reduction buffers REUSE the projector region (after __syncthreads):
//   red[16][512] floats at float-offset 0 (within Pt's 16512-float region)
//   tags/wfs at SM_HT_OFF (Ht region, also dead by then)

#define RSCALE 0.17677669529663687f   // 1/sqrt(32)

// -------------------- scratch (no allocations allowed) --------------------
__device__ int   g_mask_mode;        // 0=bool(u8), 1=int32, 2=float32
__device__ int   g_count;            // number of unmasked tokens
__device__ int   g_bcnt[64];         // per-chunk unmasked counts
__device__ int   g_boff[64];         // exclusive prefix of g_bcnt
__device__ int   g_idx[NTOK];        // compacted unmasked token indices (SORTED)
__device__ float g_bsum[Bq];         // per-batch weight sums
__device__ float g_acc[Bq * Dq];     // per-batch weighted sums (unnormalized)

// -------------------- f32x2 helpers --------------------
__device__ __forceinline__ void fma2(unsigned long long& d,
                                     unsigned long long a,
                                     unsigned long long b) {
    asm("fma.rn.f32x2 %0, %1, %2, %3;" : "=l"(d) : "l"(a), "l"(b), "l"(d));
}
__device__ __forceinline__ float2 upk(unsigned long long v) {
    float2 r;
    asm("mov.b64 {%0, %1}, %2;" : "=f"(r.x), "=f"(r.y) : "l"(v));
    return r;
}
__device__ __forceinline__ float sigmoidf(float v) {
    return 1.0f / (1.0f + __expf(-v));
}
__device__ __forceinline__ bool mask_on(const void* mask, int mm, int t) {
    if (mm == 1) return ((const int*)mask)[t] != 0;
    if (mm == 2) return ((const float*)mask)[t] != 0.0f;
    return ((const unsigned char*)mask)[t] != 0;
}

// -------------------- kernel 0: detect mask dtype -------------------------
__global__ void k_detect(const unsigned int* m) {
    int tid = threadIdx.x;            // 32 threads
    bool ai = true, af = true;
#pragma unroll
    for (int k = 0; k < 8; ++k) {
        unsigned v = m[tid * 8 + k];
        ai &= (v <= 1u);
        af &= (v == 0u || v == 0x3F800000u);
    }
    unsigned bi = __ballot_sync(0xffffffffu, ai);
    unsigned bf = __ballot_sync(0xffffffffu, af);
    if (tid == 0)
        g_mask_mode = (bi == 0xffffffffu) ? 1 : ((bf == 0xffffffffu) ? 2 : 0);
}

// -------------------- kernel 1: per-chunk counts + zero accumulators ------
// 64 blocks x 256 threads, 4 tokens/thread.
__global__ void k_count(const void* mask) {
    __shared__ int wtot[8];
    const int mm  = g_mask_mode;
    const int tid = threadIdx.x;
    const int gid = blockIdx.x * 256 + tid;

    g_acc[gid] = 0.0f;                 // 16384 threads == 16384 elements
    if (gid < Bq) g_bsum[gid] = 0.0f;

    const int t0 = blockIdx.x * 1024 + tid * 4;
    int c = 0;
#pragma unroll
    for (int k = 0; k < 4; ++k) c += mask_on(mask, mm, t0 + k) ? 1 : 0;

    // warp reduce
#pragma unroll
    for (int off = 16; off > 0; off >>= 1)
        c += __shfl_down_sync(0xffffffffu, c, off);
    if ((tid & 31) == 0) wtot[tid >> 5] = c;
    __syncthreads();
    if (tid == 0) {
        int s = 0;
#pragma unroll
        for (int w = 0; w < 8; ++w) s += wtot[w];
        g_bcnt[blockIdx.x] = s;
    }
}

// -------------------- kernel 2: scan chunk counts --------------------------
__global__ void k_scan() {
    __shared__ int wsum;
    const int tid  = threadIdx.x;   // 64 threads
    const int lane = tid & 31;
    const int wid  = tid >> 5;
    int v = g_bcnt[tid];
    int x = v;
#pragma unroll
    for (int off = 1; off < 32; off <<= 1) {
        int y = __shfl_up_sync(0xffffffffu, x, off);
        if (lane >= off) x += y;
    }
    if (wid == 0 && lane == 31) wsum = x;
    __syncthreads();
    int incl = x + (wid == 1 ? wsum : 0);
    g_boff[tid] = incl - v;          // exclusive prefix
    if (tid == 63) g_count = incl;
}

// -------------------- kernel 3: ordered fill -------------------------------
__global__ void k_fill(const void* mask) {
    __shared__ int woff[8];
    const int mm   = g_mask_mode;
    const int tid  = threadIdx.x;
    const int lane = tid & 31;
    const int wid  = tid >> 5;
    const int t0   = blockIdx.x * 1024 + tid * 4;

    bool on[4];
    int c = 0;
#pragma unroll
    for (int k = 0; k < 4; ++k) { on[k] = mask_on(mask, mm, t0 + k); c += on[k]; }

    // exclusive scan of c across 256 threads
    int x = c;
#pragma unroll
    for (int off = 1; off < 32; off <<= 1) {
        int y = __shfl_up_sync(0xffffffffu, x, off);
        if (lane >= off) x += y;
    }
    if (lane == 31) woff[wid] = x;
    __syncthreads();
    int wbase = 0;
#pragma unroll
    for (int w = 0; w < 8; ++w) wbase += (w < wid) ? woff[w] : 0;
    int pos = g_boff[blockIdx.x] + wbase + (x - c);
#pragma unroll
    for (int k = 0; k < 4; ++k)
        if (on[k]) g_idx[pos++] = t0 + k;
}

// -------------------- kernel 4: weight chain + fused weighted sum ----------
// Per block: 256 threads = 8 warps, 8 tokens per warp; tokens SORTED so a
// block's 64 tokens span at most 2 batches.
__global__ void __launch_bounds__(256) k_main(const float* __restrict__ inp,
                                              const float* __restrict__ proj,
                                              const float* __restrict__ hid,
                                              const float* __restrict__ ev) {
    extern __shared__ float sm[];
    const int tid  = threadIdx.x;
    const int lane = tid & 31;
    const int wid  = tid >> 5;

    const int count = g_count;
    if ((int)blockIdx.x * 64 >= count) return;

    // Stage transposed projector Pt[h][d], padded stride 516
    for (int i = tid; i < Dq * Hq; i += 256) {
        int d = i >> 5, h = i & 31;
        sm[SM_PT_OFF + h * PT_STRIDE + d] = proj[i];
    }
    // Stage transposed hidden Ht[k][h], padded stride 36
    for (int i = tid; i < Hq * Hq; i += 256) {
        int h = i >> 5, k = i & 31;
        sm[SM_HT_OFF + k * HT_STRIDE + h] = hid[i];
    }
    const float evv = ev[lane];
    __syncthreads();

    float* Xw  = sm + SM_XS_OFF + wid * (8 * 512);
    float* Wsw = sm + SM_WS_OFF + wid * 256;

    int  tok[8];
    bool valid[8];
    const int base = blockIdx.x * 64 + wid * 8;
#pragma unroll
    for (int t = 0; t < 8; ++t) {
        int slot = base + t;
        valid[t] = slot < count;
        int sc   = valid[t] ? slot : (count - 1);
        tok[t]   = g_idx[sc];
    }

    // Stage 8 token rows (512 floats each) into shared memory
#pragma unroll
    for (int t = 0; t < 8; ++t) {
        const float4* src = (const float4*)(inp + (size_t)tok[t] * Dq);
        float4* dst = (float4*)(Xw + t * 512);
#pragma unroll
        for (int i = 0; i < 4; ++i)
            dst[i * 32 + lane] = src[i * 32 + lane];
    }
    __syncwarp();

    // ---- projector: p[h] = sum_d x[d] * P[d][h], lane = h, pairs over d ----
    unsigned long long acc[8];
#pragma unroll
    for (int t = 0; t < 8; ++t) acc[t] = 0ull;

    const float* PtRow = sm + SM_PT_OFF + lane * PT_STRIDE;
#pragma unroll 2
    for (int d0 = 0; d0 < 512; d0 += 8) {
        ulonglong2 pA = *(const ulonglong2*)(PtRow + d0);
        ulonglong2 pB = *(const ulonglong2*)(PtRow + d0 + 4);
#pragma unroll
        for (int t = 0; t < 8; ++t) {
            const ulonglong2* xp = (const ulonglong2*)(Xw + t * 512 + d0);
            ulonglong2 xA = xp[0];
            ulonglong2 xB = xp[1];
            fma2(acc[t], xA.x, pA.x);
            fma2(acc[t], xA.y, pA.y);
            fma2(acc[t], xB.x, pB.x);
            fma2(acc[t], xB.y, pB.y);
        }
    }

    // ---- sigmoid, stash w0 for cross-lane access ----
#pragma unroll
    for (int t = 0; t < 8; ++t) {
        float2 a = upk(acc[t]);
        float w0 = sigmoidf((a.x + a.y) * RSCALE);
        Wsw[t * 32 + lane] = w0;
    }
    __syncwarp();

    // ---- hidden layer: h1[k] = sum_h w0[h] * Hd[h][k], lane = k ----
    unsigned long long acc1[8];
#pragma unroll
    for (int t = 0; t < 8; ++t) acc1[t] = 0ull;

    const float* HtRow = sm + SM_HT_OFF + lane * HT_STRIDE;
#pragma unroll
    for (int h0 = 0; h0 < 32; h0 += 8) {
        ulonglong2 hA = *(const ulonglong2*)(HtRow + h0);
        ulonglong2 hB = *(const ulonglong2*)(HtRow + h0 + 4);
#pragma unroll
        for (int t = 0; t < 8; ++t) {
            const ulonglong2* wp = (const ulonglong2*)(Wsw + t * 32 + h0);
            ulonglong2 wA = wp[0];
            ulonglong2 wB = wp[1];
            fma2(acc1[t], wA.x, hA.x);
            fma2(acc1[t], wA.y, hA.y);
            fma2(acc1[t], wB.x, hB.x);
            fma2(acc1[t], wB.y, hB.y);
        }
    }

    // ---- evaluator + final sigmoid + exp; keep wf in all lanes ----
    float wfv[8];
#pragma unroll
    for (int t = 0; t < 8; ++t) {
        float2 a1 = upk(acc1[t]);
        float w1 = sigmoidf((a1.x + a1.y) * RSCALE);
        float e = w1 * evv;
        e += __shfl_xor_sync(0xffffffffu, e, 16);
        e += __shfl_xor_sync(0xffffffffu, e, 8);
        e += __shfl_xor_sync(0xffffffffu, e, 4);
        e += __shfl_xor_sync(0xffffffffu, e, 2);
        e += __shfl_xor_sync(0xffffffffu, e, 1);
        float z = sigmoidf(e * RSCALE);
        wfv[t] = valid[t] ? __expf(z) : 0.0f;
    }

    // ---- fused weighted-sum epilogue: per-warp partials over 2 batches ----
    const int bA = tok[0] >> 11;
    const int bB = tok[7] >> 11;
    float accA[16], accB[16];
#pragma unroll
    for (int j = 0; j < 16; ++j) { accA[j] = 0.f; accB[j] = 0.f; }
    float wfsA = 0.f, wfsB = 0.f;

    if (bA == bB) {
#pragma unroll
        for (int t = 0; t < 8; ++t) {
            float wf = wfv[t];
            wfsA += wf;
            const float* xr = Xw + t * 512 + lane;
#pragma unroll
            for (int j = 0; j < 16; ++j) accA[j] += wf * xr[j * 32];
        }
    } else {
#pragma unroll
        for (int t = 0; t < 8; ++t) {
            int   bt = tok[t] >> 11;
            float wf = wfv[t];
            float wA = (bt == bA) ? wf : 0.f;
            float wB = wf - wA;
            wfsA += wA; wfsB += wB;
            const float* xr = Xw + t * 512 + lane;
#pragma unroll
            for (int j = 0; j < 16; ++j) {
                float x = xr[j * 32];
                accA[j] += wA * x;
                accB[j] += wB * x;
            }
        }
    }

    // All warps are past the projector/hidden stages once they get here;
    // sync, then REUSE the Pt/Ht shared regions for the cross-warp reduction.
    __syncthreads();
    float* red  = sm;                              // [16][512]
    int*   tags = (int*)(sm + SM_HT_OFF);          // 16 ints
    float* wfs  = sm + SM_HT_OFF + 16;             // 16 floats

#pragma unroll
    for (int j = 0; j < 16; ++j) {
        red[(wid * 2 + 0) * 512 + j * 32 + lane] = accA[j];
        red[(wid * 2 + 1) * 512 + j * 32 + lane] = accB[j];
    }
    if (lane == 0) {
        tags[wid * 2 + 0] = bA;  wfs[wid * 2 + 0] = wfsA;
        tags[wid * 2 + 1] = bB;  wfs[wid * 2 + 1] = wfsB;
    }
    __syncthreads();

    const int b0 = tags[0];
    int b1 = b0;
#pragma unroll
    for (int r = 0; r < 16; ++r) { int tg = tags[r]; if (tg != b0) b1 = tg; }

#pragma unroll
    for (int d = tid; d < 512; d += 256) {
        float s0 = 0.f, s1 = 0.f;
#pragma unroll
        for (int r = 0; r < 16; ++r) {
            float v = red[r * 512 + d];
            if (tags[r] == b0) s0 += v; else s1 += v;
        }
        atomicAdd(&g_acc[b0 * Dq + d], s0);
        if (b1 != b0) atomicAdd(&g_acc[b1 * Dq + d], s1);
    }
    if (tid == 0) {
        float s0 = 0.f, s1 = 0.f;
#pragma unroll
        for (int r = 0; r < 16; ++r) {
            if (tags[r] == b0) s0 += wfs[r]; else s1 += wfs[r];
        }
        atomicAdd(&g_bsum[b0], s0);
        if (b1 != b0) atomicAdd(&g_bsum[b1], s1);
    }
}

// -------------------- kernel 5: normalize ----------------------------------
__global__ void k_final(float* __restrict__ out) {
    int i = blockIdx.x * 256 + threadIdx.x;   // 16384 outputs
    out[i] = g_acc[i] / g_bsum[i >> 9];
}

// -------------------- launcher --------------------
extern "C" void kernel_launch(void* const* d_in, const int* in_sizes, int n_in,
                              void* d_out, int out_size) {
    const float* inp  = (const float*)d_in[0];
    const void*  mask = d_in[1];
    const float* proj = (const float*)d_in[2];
    const float* hid  = (const float*)d_in[3];
    const float* ev   = (const float*)d_in[4];
    float* out = (float*)d_out;

    cudaFuncSetAttribute(k_main, cudaFuncAttributeMaxDynamicSharedMemorySize,
                         SMEM_BYTES);

    k_detect<<<1, 32>>>((const unsigned int*)mask);
    k_count<<<64, 256>>>(mask);
    k_scan<<<1, 64>>>();
    k_fill<<<64, 256>>>(mask);
    k_main<<<NTOK / 64, 256, SMEM_BYTES>>>(inp, proj, hid, ev);
    k_final<<<Bq * Dq / 256, 256>>>(out);
}

// round 3
// speedup vs baseline: 1.4241x; 1.1451x over previous
#include <cuda_runtime.h>

// Problem constants
#define Bq 32
#define Sq 2048
#define Dq 512
#define Hq 32
#define NTOK (Bq * Sq)          // 65536

// Shared layout (float offsets) for k_main
#define SM_PT 0                  // Pt[h][d] swizzled, 32*512 = 16384
#define SM_HT 16384              // Ht[k][h] swizzled, 32*32 = 1024
#define SM_WS 17408              // per warp 288 floats (8 rows x 36), 8 warps = 2304
#define SM_TAGS 19712            // 16 int tags + 16 float wfs = 32
#define SM_XS 19744              // per warp 4128 floats (8 tokens x 516), 8 warps = 33024
#define SM_FLOATS (SM_XS + 8 * 4128)       // 52768
#define SMEM_BYTES (SM_FLOATS * 4)         // 211072 bytes

#define RSCALE 0.17677669529663687f        // 1/sqrt(32)

// -------------------- scratch --------------------
__device__ int   g_count;
__device__ int   g_bcnt[64];
__device__ int   g_idx[NTOK];
__device__ float g_bsum[Bq];
__device__ float g_acc[Bq * Dq];

// -------------------- helpers --------------------
__device__ __forceinline__ void fma2(unsigned long long& d,
                                     unsigned long long a,
                                     unsigned long long b) {
    asm("fma.rn.f32x2 %0, %1, %2, %3;" : "=l"(d) : "l"(a), "l"(b), "l"(d));
}
__device__ __forceinline__ float2 upk(unsigned long long v) {
    float2 r;
    asm("mov.b64 {%0, %1}, %2;" : "=f"(r.x), "=f"(r.y) : "l"(v));
    return r;
}
__device__ __forceinline__ float sigmoidf(float v) {
    return 1.0f / (1.0f + __expf(-v));
}
__device__ __forceinline__ bool mask_on(const void* mask, int mm, int t) {
    if (mm == 1) return ((const int*)mask)[t] != 0;
    if (mm == 2) return ((const float*)mask)[t] != 0.0f;
    return ((const unsigned char*)mask)[t] != 0;
}
// warp-0-collective mask-dtype detection over first 256 words (L2-cached)
__device__ __forceinline__ int detect_mode(const unsigned int* m, int lane) {
    bool ai = true, af = true;
#pragma unroll
    for (int k = 0; k < 8; ++k) {
        unsigned v = m[lane * 8 + k];
        ai &= (v <= 1u);
        af &= (v == 0u || v == 0x3F800000u);
    }
    unsigned bi = __ballot_sync(0xffffffffu, ai);
    unsigned bf = __ballot_sync(0xffffffffu, af);
    return (bi == 0xffffffffu) ? 1 : ((bf == 0xffffffffu) ? 2 : 0);
}

// -------------------- kernel 1: per-chunk counts + zero accumulators ------
__global__ void k_count(const void* mask) {
    __shared__ int wtot[8];
    __shared__ int s_mode;
    const int tid = threadIdx.x;
    if (tid < 32) {
        int md = detect_mode((const unsigned int*)mask, tid);
        if (tid == 0) s_mode = md;
    }
    const int gid = blockIdx.x * 256 + tid;
    g_acc[gid] = 0.0f;
    if (gid < Bq) g_bsum[gid] = 0.0f;
    __syncthreads();
    const int mm = s_mode;
    const int t0 = blockIdx.x * 1024 + tid * 4;
    int c = 0;
#pragma unroll
    for (int k = 0; k < 4; ++k) c += mask_on(mask, mm, t0 + k) ? 1 : 0;
#pragma unroll
    for (int off = 16; off > 0; off >>= 1)
        c += __shfl_down_sync(0xffffffffu, c, off);
    if ((tid & 31) == 0) wtot[tid >> 5] = c;
    __syncthreads();
    if (tid == 0) {
        int s = 0;
#pragma unroll
        for (int w = 0; w < 8; ++w) s += wtot[w];
        g_bcnt[blockIdx.x] = s;
    }
}

// -------------------- kernel 2: ordered fill (scan folded in) -------------
__global__ void k_fill(const void* mask) {
    __shared__ int woff[8];
    __shared__ int s_mode, s_boff;
    const int tid  = threadIdx.x;
    const int lane = tid & 31;
    const int wid  = tid >> 5;
    if (wid == 0) {
        int md = detect_mode((const unsigned int*)mask, lane);
        int c0 = g_bcnt[lane], c1 = g_bcnt[lane + 32];
        int bid = blockIdx.x;
        int pre = ((lane < bid) ? c0 : 0) + ((lane + 32 < bid) ? c1 : 0);
        int tot = c0 + c1;
#pragma unroll
        for (int o = 16; o; o >>= 1) {
            pre += __shfl_xor_sync(0xffffffffu, pre, o);
            tot += __shfl_xor_sync(0xffffffffu, tot, o);
        }
        if (lane == 0) {
            s_mode = md;
            s_boff = pre;
            if (blockIdx.x == 0) g_count = tot;
        }
    }
    __syncthreads();
    const int mm = s_mode;
    const int t0 = blockIdx.x * 1024 + tid * 4;
    bool on[4];
    int c = 0;
#pragma unroll
    for (int k = 0; k < 4; ++k) { on[k] = mask_on(mask, mm, t0 + k); c += on[k]; }
    int x = c;
#pragma unroll
    for (int off = 1; off < 32; off <<= 1) {
        int y = __shfl_up_sync(0xffffffffu, x, off);
        if (lane >= off) x += y;
    }
    if (lane == 31) woff[wid] = x;
    __syncthreads();
    int wbase = 0;
#pragma unroll
    for (int w = 0; w < 8; ++w) wbase += (w < wid) ? woff[w] : 0;
    int pos = s_boff + wbase + (x - c);
#pragma unroll
    for (int k = 0; k < 4; ++k)
        if (on[k]) g_idx[pos++] = t0 + k;
}

// -------------------- kernel 3: persistent weight chain + weighted sum ----
// grid = 152 blocks x 256 threads. Each block loops over 64-token slices.
// Lane tile: lane = tg*8+hg (tg=0..3, hg=0..7); per lane 2 tokens x 4 h.
__global__ void __launch_bounds__(256) k_main(const float* __restrict__ inp,
                                              const float* __restrict__ proj,
                                              const float* __restrict__ hid,
                                              const float* __restrict__ ev) {
    extern __shared__ float sm[];
    const int tid  = threadIdx.x;
    const int lane = tid & 31;
    const int wid  = tid >> 5;
    const int tg   = lane >> 3;
    const int hg   = lane & 7;

    const int count = g_count;
    const int nsl = (count + 63) >> 6;

    // Stage Pt[h][d] with XOR chunk-swizzle (key = h>>2 & 7); d-major loop so
    // writes are conflict-free within each 128B window.
    for (int i = tid; i < Dq * Hq; i += 256) {
        int h = i >> 9, d = i & 511;
        int c = d >> 2;
        sm[SM_PT + h * 512 + (((c ^ ((h >> 2) & 7)) << 2) | (d & 3))] =
            proj[d * Hq + h];
    }
    // Stage Ht[k][h] with same swizzle (key = k>>2 & 7)
    for (int i = tid; i < Hq * Hq; i += 256) {
        int k = i >> 5, h = i & 31;
        int c = h >> 2;
        sm[SM_HT + k * 32 + (((c ^ ((k >> 2) & 7)) << 2) | (h & 3))] =
            hid[h * Hq + k];
    }
    const float4 ev4 = ((const float4*)ev)[hg];
    __syncthreads();

    float* Xwarp = sm + SM_XS + wid * 4128;
    float* Wwarp = sm + SM_WS + wid * 288;
    int*   tags  = (int*)(sm + SM_TAGS);
    float* wfs   = sm + SM_TAGS + 16;

    const float* PtR0 = sm + SM_PT + (hg * 4 + 0) * 512;
    const float* PtR1 = PtR0 + 512;
    const float* PtR2 = PtR1 + 512;
    const float* PtR3 = PtR2 + 512;
    const float* HtR0 = sm + SM_HT + (hg * 4 + 0) * 32;
    const float* HtR1 = HtR0 + 32;
    const float* HtR2 = HtR1 + 32;
    const float* HtR3 = HtR2 + 32;

    for (int s = blockIdx.x; s < nsl; s += gridDim.x) {
        const int base = s * 64 + wid * 8;

        const int slot0 = base + 2 * tg;
        const bool v0 = slot0 < count;
        const bool v1 = slot0 + 1 < count;

        // ---- stage 8 token rows into Xwarp (stride 516); record wf slots ----
#pragma unroll
        for (int tt = 0; tt < 8; ++tt) {
            int sl  = base + tt;
            int tok = g_idx[min(sl, count - 1)];
            const float4* src = (const float4*)(inp + (size_t)tok * Dq);
            float4* dst = (float4*)(Xwarp + tt * 516);
#pragma unroll
            for (int i2 = 0; i2 < 4; ++i2)
                dst[i2 * 32 + lane] = src[i2 * 32 + lane];
            if (lane == 0)
                Wwarp[tt * 36 + 33] = __int_as_float(tok >> 11);  // batch id
        }
        __syncwarp();

        // ---- projector: acc2[t'][h'] pairs over d ----
        unsigned long long acc[2][4];
#pragma unroll
        for (int a = 0; a < 2; ++a)
#pragma unroll
            for (int b = 0; b < 4; ++b) acc[a][b] = 0ull;

        const float* x0 = Xwarp + 2 * tg * 516;
        const float* x1 = x0 + 516;
#pragma unroll 4
        for (int c = 0; c < 128; ++c) {
            const int d0 = c << 2;
            const int po = ((c ^ hg) << 2);
            ulonglong2 xa = *(const ulonglong2*)(x0 + d0);
            ulonglong2 xb = *(const ulonglong2*)(x1 + d0);
            ulonglong2 p0 = *(const ulonglong2*)(PtR0 + po);
            ulonglong2 p1 = *(const ulonglong2*)(PtR1 + po);
            ulonglong2 p2 = *(const ulonglong2*)(PtR2 + po);
            ulonglong2 p3 = *(const ulonglong2*)(PtR3 + po);
            fma2(acc[0][0], xa.x, p0.x); fma2(acc[0][0], xa.y, p0.y);
            fma2(acc[0][1], xa.x, p1.x); fma2(acc[0][1], xa.y, p1.y);
            fma2(acc[0][2], xa.x, p2.x); fma2(acc[0][2], xa.y, p2.y);
            fma2(acc[0][3], xa.x, p3.x); fma2(acc[0][3], xa.y, p3.y);
            fma2(acc[1][0], xb.x, p0.x); fma2(acc[1][0], xb.y, p0.y);
            fma2(acc[1][1], xb.x, p1.x); fma2(acc[1][1], xb.y, p1.y);
            fma2(acc[1][2], xb.x, p2.x); fma2(acc[1][2], xb.y, p2.y);
            fma2(acc[1][3], xb.x, p3.x); fma2(acc[1][3], xb.y, p3.y);
        }

        // ---- sigmoid -> w0 into Ws rows (float4 at hg*4) ----
#pragma unroll
        for (int tp = 0; tp < 2; ++tp) {
            float4 w4;
            float2 a0 = upk(acc[tp][0]); w4.x = sigmoidf((a0.x + a0.y) * RSCALE);
            float2 a1 = upk(acc[tp][1]); w4.y = sigmoidf((a1.x + a1.y) * RSCALE);
            float2 a2 = upk(acc[tp][2]); w4.z = sigmoidf((a2.x + a2.y) * RSCALE);
            float2 a3 = upk(acc[tp][3]); w4.w = sigmoidf((a3.x + a3.y) * RSCALE);
            *(float4*)(Wwarp + (2 * tg + tp) * 36 + hg * 4) = w4;
        }
        __syncwarp();

        // ---- hidden: acc1[t'][k'] pairs over h ----
        unsigned long long acc1[2][4];
#pragma unroll
        for (int a = 0; a < 2; ++a)
#pragma unroll
            for (int b = 0; b < 4; ++b) acc1[a][b] = 0ull;

        const float* w0a = Wwarp + 2 * tg * 36;
        const float* w0b = w0a + 36;
#pragma unroll
        for (int c = 0; c < 8; ++c) {
            const int h0 = c << 2;
            const int po = ((c ^ hg) << 2);
            ulonglong2 wa = *(const ulonglong2*)(w0a + h0);
            ulonglong2 wb = *(const ulonglong2*)(w0b + h0);
            ulonglong2 q0 = *(const ulonglong2*)(HtR0 + po);
            ulonglong2 q1 = *(const ulonglong2*)(HtR1 + po);
            ulonglong2 q2 = *(const ulonglong2*)(HtR2 + po);
            ulonglong2 q3 = *(const ulonglong2*)(HtR3 + po);
            fma2(acc1[0][0], wa.x, q0.x); fma2(acc1[0][0], wa.y, q0.y);
            fma2(acc1[0][1], wa.x, q1.x); fma2(acc1[0][1], wa.y, q1.y);
            fma2(acc1[0][2], wa.x, q2.x); fma2(acc1[0][2], wa.y, q2.y);
            fma2(acc1[0][3], wa.x, q3.x); fma2(acc1[0][3], wa.y, q3.y);
            fma2(acc1[1][0], wb.x, q0.x); fma2(acc1[1][0], wb.y, q0.y);
            fma2(acc1[1][1], wb.x, q1.x); fma2(acc1[1][1], wb.y, q1.y);
            fma2(acc1[1][2], wb.x, q2.x); fma2(acc1[1][2], wb.y, q2.y);
            fma2(acc1[1][3], wb.x, q3.x); fma2(acc1[1][3], wb.y, q3.y);
        }

        // ---- evaluator + final sigmoid + exp ----
        float wfv[2];
#pragma unroll
        for (int tp = 0; tp < 2; ++tp) {
            float2 a0 = upk(acc1[tp][0]);
            float2 a1 = upk(acc1[tp][1]);
            float2 a2 = upk(acc1[tp][2]);
            float2 a3 = upk(acc1[tp][3]);
            float e = sigmoidf((a0.x + a0.y) * RSCALE) * ev4.x +
                      sigmoidf((a1.x + a1.y) * RSCALE) * ev4.y +
                      sigmoidf((a2.x + a2.y) * RSCALE) * ev4.z +
                      sigmoidf((a3.x + a3.y) * RSCALE) * ev4.w;
            e += __shfl_xor_sync(0xffffffffu, e, 1);
            e += __shfl_xor_sync(0xffffffffu, e, 2);
            e += __shfl_xor_sync(0xffffffffu, e, 4);
            float z = sigmoidf(e * RSCALE);
            bool vv = tp ? v1 : v0;
            wfv[tp] = vv ? __expf(z) : 0.0f;
        }
        if (hg == 0) {
            Wwarp[(2 * tg + 0) * 36 + 32] = wfv[0];
            Wwarp[(2 * tg + 1) * 36 + 32] = wfv[1];
        }
        __syncwarp();

        // ---- per-warp weighted partial sums over <=2 batches ----
        const int bA = __float_as_int(Wwarp[0 * 36 + 33]);
        const int bB = __float_as_int(Wwarp[7 * 36 + 33]);
        float accA[16], accB[16];
#pragma unroll
        for (int j = 0; j < 16; ++j) { accA[j] = 0.f; accB[j] = 0.f; }
        float wfsA = 0.f, wfsB = 0.f;

        if (bA == bB) {
#pragma unroll
            for (int tt = 0; tt < 8; ++tt) {
                float wf = Wwarp[tt * 36 + 32];
                wfsA += wf;
                const float* xr = Xwarp + tt * 516 + lane;
#pragma unroll
                for (int j = 0; j < 16; ++j) accA[j] += wf * xr[j * 32];
            }
        } else {
#pragma unroll
            for (int tt = 0; tt < 8; ++tt) {
                float wf = Wwarp[tt * 36 + 32];
                int   bt = __float_as_int(Wwarp[tt * 36 + 33]);
                float wA = (bt == bA) ? wf : 0.f;
                float wB = wf - wA;
                wfsA += wA; wfsB += wB;
                const float* xr = Xwarp + tt * 516 + lane;
#pragma unroll
                for (int j = 0; j < 16; ++j) {
                    float xv = xr[j * 32];
                    accA[j] += wA * xv;
                    accB[j] += wB * xv;
                }
            }
        }

        // ---- block reduction (red overlays dead Xw region) ----
        __syncthreads();
        float* red = sm + SM_XS;
#pragma unroll
        for (int j = 0; j < 16; ++j) {
            red[(wid * 2 + 0) * 512 + j * 32 + lane] = accA[j];
            red[(wid * 2 + 1) * 512 + j * 32 + lane] = accB[j];
        }
        if (lane == 0) {
            tags[wid * 2 + 0] = bA;  wfs[wid * 2 + 0] = wfsA;
            tags[wid * 2 + 1] = bB;  wfs[wid * 2 + 1] = wfsB;
        }
        __syncthreads();

        const int b0 = tags[0];
        int b1 = b0;
#pragma unroll
        for (int r = 0; r < 16; ++r) { int t2 = tags[r]; if (t2 != b0) b1 = t2; }

#pragma unroll
        for (int d = tid; d < 512; d += 256) {
            float s0 = 0.f, s1 = 0.f;
#pragma unroll
            for (int r = 0; r < 16; ++r) {
                float v = red[r * 512 + d];
                if (tags[r] == b0) s0 += v; else s1 += v;
            }
            atomicAdd(&g_acc[b0 * Dq + d], s0);
            if (b1 != b0) atomicAdd(&g_acc[b1 * Dq + d], s1);
        }
        if (tid == 0) {
            float s0 = 0.f, s1 = 0.f;
#pragma unroll
            for (int r = 0; r < 16; ++r) {
                if (tags[r] == b0) s0 += wfs[r]; else s1 += wfs[r];
            }
            atomicAdd(&g_bsum[b0], s0);
            if (b1 != b0) atomicAdd(&g_bsum[b1], s1);
        }
        __syncthreads();   // red reads done before next slice restages Xw
    }
}

// -------------------- kernel 4: normalize ----------------------------------
__global__ void k_final(float* __restrict__ out) {
    int i = blockIdx.x * 256 + threadIdx.x;
    out[i] = g_acc[i] / g_bsum[i >> 9];
}

// -------------------- launcher --------------------
extern "C" void kernel_launch(void* const* d_in, const int* in_sizes, int n_in,
                              void* d_out, int out_size) {
    const float* inp  = (const float*)d_in[0];
    const void*  mask = d_in[1];
    const float* proj = (const float*)d_in[2];
    const float* hid  = (const float*)d_in[3];
    const float* ev   = (const float*)d_in[4];
    float* out = (float*)d_out;

    cudaFuncSetAttribute(k_main, cudaFuncAttributeMaxDynamicSharedMemorySize,
                         SMEM_BYTES);

    k_count<<<64, 256>>>(mask);
    k_fill<<<64, 256>>>(mask);
    k_main<<<152, 256, SMEM_BYTES>>>(inp, proj, hid, ev);
    k_final<<<Bq * Dq / 256, 256>>>(out);
}